// round 5
// baseline (speedup 1.0000x reference)
#include <cuda_runtime.h>
#include <cuda_bf16.h>
#include <math.h>

// Problem constants
// B=2, N=2048, H=256, heads=8, d=32, WIN=32, WIN_LEN=65
#define BB 2
#define NN 2048
#define HH 256
#define NH 8
#define HD 32
#define WIN 32
#define WLEN 65
#define BHN (BB*NH)         // 16
#define BN (BB*NN)          // 4096

// ---------------- scratch (device globals; no allocation allowed) -------------
__device__ float g_q[BHN*NN*HD];        // (bh, n, d)
__device__ float g_k[BHN*NN*HD];
__device__ float g_v[BHN*NN*HD];
__device__ float g_vp[BN*3*512];        // vec_proj (bn*3+c, 512)
__device__ float g_vd[BN*HH];           // vec_dot (bn, j)
__device__ float g_vn[BN*HH];           // vec_norm
__device__ float g_xout[BN*HH];         // x_out (bn, H)
__device__ float g_vaggr[BN*3*HH];      // (bn, c, H)
__device__ float g_gate[BN*HH];

// ======================= SGEMM: QKV (M=4096, N=256, K=256) ====================
// A = x channel 0 : row m at x + m*1024.  z selects Wq/Wk/Wv. Scatter epilogue.
__global__ __launch_bounds__(256) void gemm_qkv_kernel(
    const float* __restrict__ x,
    const float* __restrict__ Wq, const float* __restrict__ Wk, const float* __restrict__ Wv,
    const float* __restrict__ bq, const float* __restrict__ bk, const float* __restrict__ bv)
{
    __shared__ float As[64][17];
    __shared__ float Bs[16][64];
    int z = blockIdx.z;
    const float* W    = (z==0) ? Wq : (z==1 ? Wk : Wv);
    const float* bias = (z==0) ? bq : (z==1 ? bk : bv);
    float* dst        = (z==0) ? g_q : (z==1 ? g_k : g_v);

    int m0 = blockIdx.x*64, n0 = blockIdx.y*64;
    int tid = threadIdx.x;
    int tx = tid & 15, ty = tid >> 4;
    int la_m = tid >> 2, la_k = (tid & 3) << 2;
    int lb_k = tid >> 4, lb_n = (tid & 15) << 2;

    float acc[4][4];
#pragma unroll
    for (int i=0;i<4;i++)
#pragma unroll
        for (int j=0;j<4;j++) acc[i][j]=0.f;

    for (int k0=0;k0<256;k0+=16) {
        float4 av = *(const float4*)(x + (size_t)(m0+la_m)*1024 + k0 + la_k);
        As[la_m][la_k+0]=av.x; As[la_m][la_k+1]=av.y; As[la_m][la_k+2]=av.z; As[la_m][la_k+3]=av.w;
        float4 bv4 = *(const float4*)(W + (size_t)(k0+lb_k)*256 + n0 + lb_n);
        *(float4*)&Bs[lb_k][lb_n] = bv4;
        __syncthreads();
#pragma unroll
        for (int kk=0;kk<16;kk++) {
            float a0=As[ty*4+0][kk], a1=As[ty*4+1][kk], a2=As[ty*4+2][kk], a3=As[ty*4+3][kk];
            float4 b = *(const float4*)&Bs[kk][tx*4];
            acc[0][0]+=a0*b.x; acc[0][1]+=a0*b.y; acc[0][2]+=a0*b.z; acc[0][3]+=a0*b.w;
            acc[1][0]+=a1*b.x; acc[1][1]+=a1*b.y; acc[1][2]+=a1*b.z; acc[1][3]+=a1*b.w;
            acc[2][0]+=a2*b.x; acc[2][1]+=a2*b.y; acc[2][2]+=a2*b.z; acc[2][3]+=a2*b.w;
            acc[3][0]+=a3*b.x; acc[3][1]+=a3*b.y; acc[3][2]+=a3*b.z; acc[3][3]+=a3*b.w;
        }
        __syncthreads();
    }
#pragma unroll
    for (int i=0;i<4;i++) {
        int m = m0 + ty*4 + i;
        int b = m >> 11, n = m & 2047;
#pragma unroll
        for (int j=0;j<4;j++) {
            int col = n0 + tx*4 + j;
            int h = col >> 5, dd = col & 31;
            dst[(((size_t)(b*NH + h))*NN + n)*HD + dd] = acc[i][j] + bias[col];
        }
    }
}

// ================= SGEMM: vec_proj (M=12288, N=512, K=256) ====================
__global__ __launch_bounds__(256) void gemm_vp_kernel(
    const float* __restrict__ x, const float* __restrict__ Wvec)
{
    __shared__ float As[64][17];
    __shared__ float Bs[16][64];
    int m0 = blockIdx.x*64, n0 = blockIdx.y*64;
    int tid = threadIdx.x;
    int tx = tid & 15, ty = tid >> 4;
    int la_m = tid >> 2, la_k = (tid & 3) << 2;
    int lb_k = tid >> 4, lb_n = (tid & 15) << 2;

    float acc[4][4];
#pragma unroll
    for (int i=0;i<4;i++)
#pragma unroll
        for (int j=0;j<4;j++) acc[i][j]=0.f;

    int m = m0 + la_m;
    const float* arow = x + ((size_t)(m/3)*4 + 1 + (m%3))*256;

    for (int k0=0;k0<256;k0+=16) {
        float4 av = *(const float4*)(arow + k0 + la_k);
        As[la_m][la_k+0]=av.x; As[la_m][la_k+1]=av.y; As[la_m][la_k+2]=av.z; As[la_m][la_k+3]=av.w;
        float4 bv4 = *(const float4*)(Wvec + (size_t)(k0+lb_k)*512 + n0 + lb_n);
        *(float4*)&Bs[lb_k][lb_n] = bv4;
        __syncthreads();
#pragma unroll
        for (int kk=0;kk<16;kk++) {
            float a0=As[ty*4+0][kk], a1=As[ty*4+1][kk], a2=As[ty*4+2][kk], a3=As[ty*4+3][kk];
            float4 b = *(const float4*)&Bs[kk][tx*4];
            acc[0][0]+=a0*b.x; acc[0][1]+=a0*b.y; acc[0][2]+=a0*b.z; acc[0][3]+=a0*b.w;
            acc[1][0]+=a1*b.x; acc[1][1]+=a1*b.y; acc[1][2]+=a1*b.z; acc[1][3]+=a1*b.w;
            acc[2][0]+=a2*b.x; acc[2][1]+=a2*b.y; acc[2][2]+=a2*b.z; acc[2][3]+=a2*b.w;
            acc[3][0]+=a3*b.x; acc[3][1]+=a3*b.y; acc[3][2]+=a3*b.z; acc[3][3]+=a3*b.w;
        }
        __syncthreads();
    }
#pragma unroll
    for (int i=0;i<4;i++) {
        int mm = m0 + ty*4 + i;
#pragma unroll
        for (int j=0;j<4;j++) {
            int col = n0 + tx*4 + j;
            g_vp[(size_t)mm*512 + col] = acc[i][j];
        }
    }
}

// ============== elementwise: vec_dot and vec_norm (per bn, j) =================
__global__ void vecdot_norm_kernel(const float* __restrict__ x)
{
    int bn = blockIdx.x, j = threadIdx.x;
    float vd = 0.f, s = 0.f;
#pragma unroll
    for (int c=0;c<3;c++) {
        float a  = g_vp[((size_t)bn*3 + c)*512 + j];
        float b2 = g_vp[((size_t)bn*3 + c)*512 + 256 + j];
        vd += a*b2;
        float xv = x[((size_t)bn*4 + 1 + c)*256 + j];
        s += xv*xv;
    }
    g_vd[(size_t)bn*256 + j] = vd;
    g_vn[(size_t)bn*256 + j] = sqrtf(s);
}

// ===================== sliding-window attention ===============================
// Block: (t, bh). TQ=128 queries, 192 staged rows (k/v: 32f pad36, vec: 96f pad100).
#define ROWS 192
#define KSTR 36
#define VSTR 100
#define WSTR 67
__global__ __launch_bounds__(128) void attn_kernel(
    const float* __restrict__ x, float* __restrict__ attn_out)
{
    extern __shared__ float sm[];
    float* ks   = sm;                    // 192*36 = 6912
    float* vs   = ks + ROWS*KSTR;        // 6912
    float* vecs = vs + ROWS*KSTR;        // 192*100 = 19200
    float* wts  = vecs + ROWS*VSTR;      // 128*67  = 8576

    int t  = blockIdx.x;
    int bh = blockIdx.y;
    int b = bh >> 3, h = bh & 7;
    int n_base = t*128;

    // stage k, v
    for (int idx = threadIdx.x; idx < ROWS*32; idx += 128) {
        int r = idx >> 5, d = idx & 31;
        int ng = n_base - WIN + r;
        float kv = 0.f, vv = 0.f;
        if (ng >= 0 && ng < NN) {
            size_t o = ((size_t)bh*NN + ng)*HD + d;
            kv = g_k[o]; vv = g_v[o];
        }
        ks[r*KSTR + d] = kv;
        vs[r*KSTR + d] = vv;
    }
    // stage vec windows (3 components of this head)
    for (int idx = threadIdx.x; idx < ROWS*96; idx += 128) {
        int r = idx / 96, jj = idx - r*96;
        int c = jj >> 5, dd = jj & 31;
        int ng = n_base - WIN + r;
        float vv = 0.f;
        if (ng >= 0 && ng < NN)
            vv = x[(((size_t)b*NN + ng)*4 + 1 + c)*256 + h*HD + dd];
        vecs[r*VSTR + jj] = vv;
    }
    __syncthreads();

    int qi = threadIdx.x;
    int n  = n_base + qi;

    float4 q[8];
    const float4* qp = (const float4*)(g_q + ((size_t)bh*NN + n)*HD);
#pragma unroll
    for (int i=0;i<8;i++) q[i] = qp[i];

    const float scale = 0.17677669529663687f;  // 1/sqrt(32)

    // scores (zero-padded rows give score 0, matching the reference's zero-pad)
    float mx = -1e30f;
    for (int w=0; w<WLEN; w++) {
        const float4* kr = (const float4*)(ks + (qi+w)*KSTR);
        float s = 0.f;
#pragma unroll
        for (int i=0;i<8;i++) {
            float4 kv = kr[i];
            s += q[i].x*kv.x + q[i].y*kv.y + q[i].z*kv.z + q[i].w*kv.w;
        }
        s *= scale;
        wts[qi*WSTR + w] = s;
        mx = fmaxf(mx, s);
    }
    float sum = 0.f;
    for (int w=0; w<WLEN; w++) {
        float e = __expf(wts[qi*WSTR + w] - mx);
        wts[qi*WSTR + w] = e;
        sum += e;
    }
    float inv = 1.f/sum;
    for (int w=0; w<WLEN; w++) wts[qi*WSTR + w] *= inv;
    __syncthreads();

    // coalesced write of attention weights: (bh, n, w) contiguous over the tile
    {
        float* ao = attn_out + ((size_t)bh*NN + n_base)*WLEN;
        for (int idx = threadIdx.x; idx < 128*WLEN; idx += 128) {
            int q2 = idx / WLEN, w = idx - q2*WLEN;
            ao[idx] = wts[q2*WSTR + w];
        }
    }

    // x aggregation (d=32)
    {
        float4 acc[8];
#pragma unroll
        for (int i=0;i<8;i++) acc[i] = make_float4(0.f,0.f,0.f,0.f);
        for (int w=0; w<WLEN; w++) {
            float wv = wts[qi*WSTR + w];
            const float4* vr = (const float4*)(vs + (qi+w)*KSTR);
#pragma unroll
            for (int i=0;i<8;i++) {
                float4 v = vr[i];
                acc[i].x += wv*v.x; acc[i].y += wv*v.y; acc[i].z += wv*v.z; acc[i].w += wv*v.w;
            }
        }
        float4* xo = (float4*)(g_xout + ((size_t)b*NN + n)*HH + h*HD);
#pragma unroll
        for (int i=0;i<8;i++) xo[i] = acc[i];
    }

    // vec aggregation (3 passes of 32 dims)
#pragma unroll
    for (int p=0;p<3;p++) {
        float4 acc[8];
#pragma unroll
        for (int i=0;i<8;i++) acc[i] = make_float4(0.f,0.f,0.f,0.f);
        for (int w=0; w<WLEN; w++) {
            float wv = wts[qi*WSTR + w];
            const float4* vr = (const float4*)(vecs + (qi+w)*VSTR + p*32);
#pragma unroll
            for (int i=0;i<8;i++) {
                float4 v = vr[i];
                acc[i].x += wv*v.x; acc[i].y += wv*v.y; acc[i].z += wv*v.z; acc[i].w += wv*v.w;
            }
        }
        float4* vo = (float4*)(g_vaggr + (((size_t)b*NN + n)*3 + p)*HH + h*HD);
#pragma unroll
        for (int i=0;i<8;i++) vo[i] = acc[i];
    }
}

// =============== SGEMM: gate (M=4096, N=256, K=512, sigmoid) ==================
__global__ __launch_bounds__(256) void gemm_gate_kernel(
    const float* __restrict__ p_ad, const float* __restrict__ p_an,
    const float* __restrict__ Wg, const float* __restrict__ bg)
{
    __shared__ float As[64][17];
    __shared__ float Bs[16][64];
    float ad = *p_ad, an = *p_an;
    int m0 = blockIdx.x*64, n0 = blockIdx.y*64;
    int tid = threadIdx.x;
    int tx = tid & 15, ty = tid >> 4;
    int la_m = tid >> 2, la_k = (tid & 3) << 2;
    int lb_k = tid >> 4, lb_n = (tid & 15) << 2;

    float acc[4][4];
#pragma unroll
    for (int i=0;i<4;i++)
#pragma unroll
        for (int j=0;j<4;j++) acc[i][j]=0.f;

    int m = m0 + la_m;
    for (int k0=0;k0<512;k0+=16) {
        int i0 = k0 + la_k;
        float4 av;
        if (i0 < 256) {
            av = *(const float4*)(g_vd + (size_t)m*256 + i0);
            av.x*=ad; av.y*=ad; av.z*=ad; av.w*=ad;
        } else {
            av = *(const float4*)(g_vn + (size_t)m*256 + i0 - 256);
            av.x*=an; av.y*=an; av.z*=an; av.w*=an;
        }
        As[la_m][la_k+0]=av.x; As[la_m][la_k+1]=av.y; As[la_m][la_k+2]=av.z; As[la_m][la_k+3]=av.w;
        float4 bv4 = *(const float4*)(Wg + (size_t)(k0+lb_k)*256 + n0 + lb_n);
        *(float4*)&Bs[lb_k][lb_n] = bv4;
        __syncthreads();
#pragma unroll
        for (int kk=0;kk<16;kk++) {
            float a0=As[ty*4+0][kk], a1=As[ty*4+1][kk], a2=As[ty*4+2][kk], a3=As[ty*4+3][kk];
            float4 b = *(const float4*)&Bs[kk][tx*4];
            acc[0][0]+=a0*b.x; acc[0][1]+=a0*b.y; acc[0][2]+=a0*b.z; acc[0][3]+=a0*b.w;
            acc[1][0]+=a1*b.x; acc[1][1]+=a1*b.y; acc[1][2]+=a1*b.z; acc[1][3]+=a1*b.w;
            acc[2][0]+=a2*b.x; acc[2][1]+=a2*b.y; acc[2][2]+=a2*b.z; acc[2][3]+=a2*b.w;
            acc[3][0]+=a3*b.x; acc[3][1]+=a3*b.y; acc[3][2]+=a3*b.z; acc[3][3]+=a3*b.w;
        }
        __syncthreads();
    }
#pragma unroll
    for (int i=0;i<4;i++) {
        int mm = m0 + ty*4 + i;
#pragma unroll
        for (int j=0;j<4;j++) {
            int col = n0 + tx*4 + j;
            float v = acc[i][j] + bg[col];
            g_gate[(size_t)mm*256 + col] = 1.f/(1.f + __expf(-v));
        }
    }
}

// ===== SGEMM: out-proj (M=4096, N=256 x 3 chunks, K=256) + fused x_updated ====
__global__ __launch_bounds__(256) void gemm_final_kernel(
    const float* __restrict__ Wo, const float* __restrict__ bo, float* __restrict__ out)
{
    __shared__ float As[64][17];
    __shared__ float Bs[3][16][64];
    int m0 = blockIdx.x*64, n0 = blockIdx.y*64;
    int tid = threadIdx.x;
    int tx = tid & 15, ty = tid >> 4;
    int la_m = tid >> 2, la_k = (tid & 3) << 2;
    int lb_k = tid >> 4, lb_n = (tid & 15) << 2;

    float acc1[4][4], acc2[4][4], acc3[4][4];
#pragma unroll
    for (int i=0;i<4;i++)
#pragma unroll
        for (int j=0;j<4;j++) { acc1[i][j]=0.f; acc2[i][j]=0.f; acc3[i][j]=0.f; }

    for (int k0=0;k0<256;k0+=16) {
        float4 av = *(const float4*)(g_xout + (size_t)(m0+la_m)*256 + k0 + la_k);
        As[la_m][la_k+0]=av.x; As[la_m][la_k+1]=av.y; As[la_m][la_k+2]=av.z; As[la_m][la_k+3]=av.w;
#pragma unroll
        for (int ch=0; ch<3; ch++) {
            float4 bv4 = *(const float4*)(Wo + (size_t)(k0+lb_k)*768 + ch*256 + n0 + lb_n);
            *(float4*)&Bs[ch][lb_k][lb_n] = bv4;
        }
        __syncthreads();
#pragma unroll
        for (int kk=0;kk<16;kk++) {
            float a0=As[ty*4+0][kk], a1=As[ty*4+1][kk], a2=As[ty*4+2][kk], a3=As[ty*4+3][kk];
            float4 b1 = *(const float4*)&Bs[0][kk][tx*4];
            float4 b2 = *(const float4*)&Bs[1][kk][tx*4];
            float4 b3 = *(const float4*)&Bs[2][kk][tx*4];
            acc1[0][0]+=a0*b1.x; acc1[0][1]+=a0*b1.y; acc1[0][2]+=a0*b1.z; acc1[0][3]+=a0*b1.w;
            acc1[1][0]+=a1*b1.x; acc1[1][1]+=a1*b1.y; acc1[1][2]+=a1*b1.z; acc1[1][3]+=a1*b1.w;
            acc1[2][0]+=a2*b1.x; acc1[2][1]+=a2*b1.y; acc1[2][2]+=a2*b1.z; acc1[2][3]+=a2*b1.w;
            acc1[3][0]+=a3*b1.x; acc1[3][1]+=a3*b1.y; acc1[3][2]+=a3*b1.z; acc1[3][3]+=a3*b1.w;
            acc2[0][0]+=a0*b2.x; acc2[0][1]+=a0*b2.y; acc2[0][2]+=a0*b2.z; acc2[0][3]+=a0*b2.w;
            acc2[1][0]+=a1*b2.x; acc2[1][1]+=a1*b2.y; acc2[1][2]+=a1*b2.z; acc2[1][3]+=a1*b2.w;
            acc2[2][0]+=a2*b2.x; acc2[2][1]+=a2*b2.y; acc2[2][2]+=a2*b2.z; acc2[2][3]+=a2*b2.w;
            acc2[3][0]+=a3*b2.x; acc2[3][1]+=a3*b2.y; acc2[3][2]+=a3*b2.z; acc2[3][3]+=a3*b2.w;
            acc3[0][0]+=a0*b3.x; acc3[0][1]+=a0*b3.y; acc3[0][2]+=a0*b3.z; acc3[0][3]+=a0*b3.w;
            acc3[1][0]+=a1*b3.x; acc3[1][1]+=a1*b3.y; acc3[1][2]+=a1*b3.z; acc3[1][3]+=a1*b3.w;
            acc3[2][0]+=a2*b3.x; acc3[2][1]+=a2*b3.y; acc3[2][2]+=a2*b3.z; acc3[2][3]+=a2*b3.w;
            acc3[3][0]+=a3*b3.x; acc3[3][1]+=a3*b3.y; acc3[3][2]+=a3*b3.z; acc3[3][3]+=a3*b3.w;
        }
        __syncthreads();
    }
#pragma unroll
    for (int i=0;i<4;i++) {
        int m = m0 + ty*4 + i;
#pragma unroll
        for (int j=0;j<4;j++) {
            int col = n0 + tx*4 + j;
            float o1 = acc1[i][j] + bo[col];
            float o2 = acc2[i][j] + bo[256 + col];
            float o3 = acc3[i][j] + bo[512 + col];
            float vd = g_vd[(size_t)m*256 + col];
            float vn = g_vn[(size_t)m*256 + col];
            out[((size_t)m*4 + 0)*256 + col] = vd*o1 + vn*o2 + o3;  // channel 0
        }
    }
}

// ===================== vec_combined -> output channels 1..3 ===================
__global__ void combine_kernel(const float* __restrict__ x, float* __restrict__ out)
{
    int idx = blockIdx.x*blockDim.x + threadIdx.x;
    if (idx >= BN*3*256) return;
    int j  = idx & 255;
    int c  = (idx >> 8) % 3;
    int bn = idx / 768;
    float g  = g_gate[(size_t)bn*256 + j];
    float va = g_vaggr[idx];
    size_t xo = ((size_t)bn*4 + 1 + c)*256 + j;
    out[xo] = g*va + x[xo];
}

// ================================ launch ======================================
extern "C" void kernel_launch(void* const* d_in, const int* in_sizes, int n_in,
                              void* d_out, int out_size)
{
    const float* x    = (const float*)d_in[0];
    const float* Wq   = (const float*)d_in[1];
    const float* bq   = (const float*)d_in[2];
    const float* Wk   = (const float*)d_in[3];
    const float* bk   = (const float*)d_in[4];
    const float* Wv   = (const float*)d_in[5];
    const float* bv   = (const float*)d_in[6];
    const float* Wo   = (const float*)d_in[7];
    const float* bo   = (const float*)d_in[8];
    const float* Wvec = (const float*)d_in[9];
    const float* p_ad = (const float*)d_in[10];
    const float* p_an = (const float*)d_in[11];
    const float* Wg   = (const float*)d_in[12];
    const float* bg   = (const float*)d_in[13];

    float* out = (float*)d_out;
    float* attn_out = out + (size_t)BN*4*256;   // x_final first, then attn_weights

    const int attn_smem = (ROWS*KSTR*2 + ROWS*VSTR + 128*WSTR) * 4;  // 166400 B
    cudaFuncSetAttribute(attn_kernel, cudaFuncAttributeMaxDynamicSharedMemorySize, attn_smem);

    gemm_qkv_kernel<<<dim3(64,4,3), 256>>>(x, Wq, Wk, Wv, bq, bk, bv);
    gemm_vp_kernel<<<dim3(192,8), 256>>>(x, Wvec);
    vecdot_norm_kernel<<<BN, 256>>>(x);
    attn_kernel<<<dim3(16,16), 128, attn_smem>>>(x, attn_out);
    gemm_gate_kernel<<<dim3(64,4), 256>>>(p_ad, p_an, Wg, bg);
    gemm_final_kernel<<<dim3(64,4), 256>>>(Wo, bo, out);
    combine_kernel<<<(BN*3*256 + 255)/256, 256>>>(x, out);
}